// round 15
// baseline (speedup 1.0000x reference)
#include <cuda_runtime.h>
#include <cuda_bf16.h>
#include <cstdint>
#include <cstddef>

#define T_STEPS 1024
#define NENV    256
#define DIM     128
#define FEAT    128
#define GI_COLS 384   // 3*FEAT

typedef unsigned long long ull;

// Scratch for precomputed input projections gi = obs @ Wi + bi  : [T*N, 3F]
__device__ float g_gi[(size_t)T_STEPS * NENV * GI_COLS];

// ---- packed f32x2 helpers ------------------------------------------------
#define FMA2(d, a, b, c) \
    asm("fma.rn.f32x2 %0, %1, %2, %3;" : "=l"(d) : "l"(a), "l"(b), "l"(c))

__device__ __forceinline__ ull pack2(float lo, float hi) {
    ull r;
    asm("mov.b64 %0, {%1, %2};" : "=l"(r)
        : "r"(__float_as_uint(lo)), "r"(__float_as_uint(hi)));
    return r;
}
__device__ __forceinline__ void unpack2(float& lo, float& hi, ull v) {
    unsigned a, b;
    asm("mov.b64 {%0, %1}, %2;" : "=r"(a), "=r"(b) : "l"(v));
    lo = __uint_as_float(a);
    hi = __uint_as_float(b);
}
__device__ __forceinline__ float tanhapx(float x) {
    float y;
    asm("tanh.approx.f32 %0, %1;" : "=f"(y) : "f"(x));
    return y;
}
__device__ __forceinline__ float sigmoidapx(float x) {
    return fmaf(0.5f, tanhapx(0.5f * x), 0.5f);
}
__device__ __forceinline__ unsigned smem_u32(const void* p) {
    unsigned a;
    asm("{ .reg .u64 t; cvta.to.shared.u64 t, %1; cvt.u32.u64 %0, t; }"
        : "=r"(a) : "l"(p));
    return a;
}
#define CP_ASYNC16(dst_u32, src_ptr) \
    asm volatile("cp.async.cg.shared.global [%0], [%1], 16;" \
                 :: "r"(dst_u32), "l"(src_ptr))
#define CP_COMMIT() asm volatile("cp.async.commit_group;")
#define CP_WAIT1()  asm volatile("cp.async.wait_group 1;")

// ---- bf16 split helpers ---------------------------------------------------
__device__ __forceinline__ unsigned pkbf2(__nv_bfloat16 b0, __nv_bfloat16 b1) {
    return ((unsigned)__bfloat16_as_ushort(b1) << 16) |
           (unsigned)__bfloat16_as_ushort(b0);
}

#define MMA16816(d, a, b) \
    asm volatile("mma.sync.aligned.m16n8k16.row.col.f32.bf16.bf16.f32 " \
        "{%0,%1,%2,%3}, {%4,%5,%6,%7}, {%8,%9}, {%0,%1,%2,%3};" \
        : "+f"((d)[0]), "+f"((d)[1]), "+f"((d)[2]), "+f"((d)[3]) \
        : "r"((a)[0]), "r"((a)[1]), "r"((a)[2]), "r"((a)[3]), \
          "r"((b)[0]), "r"((b)[1]))

#define LDSM_X4(r0, r1, r2, r3, addr) \
    asm volatile("ldmatrix.sync.aligned.m8n8.x4.shared.b16 {%0,%1,%2,%3}, [%4];" \
        : "=r"(r0), "=r"(r1), "=r"(r2), "=r"(r3) : "r"(addr))

// ---------------------------------------------------------------------------
// Phase 1: gi = obs @ Wi + bi  via bf16 3-term split tensor-core GEMM.
//   A@B ~= Ah Bh + Al Bh + Ah Bl   (fp32 accumulate; rel err ~1e-5)
// CTA: 128m block, full K in SMEM, loops over 3 n-blocks of 128.
// 256 threads = 8 warps (2m x 4n), warp tile 64x32, mma m16n8k16.
// Fragment loads via ldmatrix.x4 (12 LDSM/k-step vs 48 scalar LDS).
// SMEM word stride 68 per row -> LDSM rows hit banks (4r)%32, conflict-free.
// ---------------------------------------------------------------------------
#define WST 68   // row stride in 32-bit words (= 136 bf16)

__global__ __launch_bounds__(256)
void gemm_gi_bf16_kernel(const float* __restrict__ A,
                         const float* __restrict__ B,
                         const float* __restrict__ bias) {
    extern __shared__ unsigned smw[];
    unsigned* Ahi = smw;                  // [128][WST]
    unsigned* Alo = Ahi + 128 * WST;
    unsigned* Bhi = Alo + 128 * WST;      // [n][k-pairs]
    unsigned* Blo = Bhi + 128 * WST;

    const int t    = threadIdx.x;
    const int m0   = blockIdx.x * 128;
    const int warp = t >> 5;
    const int lane = t & 31;
    const int g    = lane >> 2;      // 0..7
    const int q    = lane & 3;       // 0..3
    const int wm   = warp >> 2;      // 0..1
    const int wn   = warp & 3;       // 0..3

    // ---- Fill A (obs block, full K), split hi/lo ----
    #pragma unroll
    for (int i = 0; i < 16; i++) {
        int idx = t + i * 256;            // 0..4095 float4 slots
        int m   = idx >> 5;               // 0..127
        int kc  = (idx & 31) << 2;        // 0..124
        float4 v = *reinterpret_cast<const float4*>(
            A + (size_t)(m0 + m) * 128 + kc);
        __nv_bfloat16 hx = __float2bfloat16(v.x), hy = __float2bfloat16(v.y);
        __nv_bfloat16 hz = __float2bfloat16(v.z), hw = __float2bfloat16(v.w);
        Ahi[m * WST + (kc >> 1)]     = pkbf2(hx, hy);
        Ahi[m * WST + (kc >> 1) + 1] = pkbf2(hz, hw);
        __nv_bfloat16 lx = __float2bfloat16(v.x - __bfloat162float(hx));
        __nv_bfloat16 ly = __float2bfloat16(v.y - __bfloat162float(hy));
        __nv_bfloat16 lz = __float2bfloat16(v.z - __bfloat162float(hz));
        __nv_bfloat16 lw = __float2bfloat16(v.w - __bfloat162float(hw));
        Alo[m * WST + (kc >> 1)]     = pkbf2(lx, ly);
        Alo[m * WST + (kc >> 1) + 1] = pkbf2(lz, lw);
    }

    // ldmatrix lane base offsets (bytes)
    const uint32_t sAhi = smem_u32(Ahi);
    const uint32_t sAlo = smem_u32(Alo);
    const uint32_t sBhi = smem_u32(Bhi);
    const uint32_t sBlo = smem_u32(Blo);
    // A: 16x16 tile; lanes 0-15 -> rows (left 8 cols), 16-31 -> rows (right)
    const uint32_t aoff =
        ((uint32_t)(wm * 64 + (lane & 15)) * WST + (uint32_t)(lane >> 4) * 4) * 4u;
    // B: two 8x16 n-tiles per x4; lanes 0-7 ns0/left, 8-15 ns0/right,
    //    16-23 ns1/left, 24-31 ns1/right
    const uint32_t boff =
        ((uint32_t)(wn * 32 + (lane & 7) + ((lane >> 4) << 3)) * WST +
         (uint32_t)((lane >> 3) & 1) * 4) * 4u;

    for (int nb = 0; nb < 3; nb++) {
        const int n0 = nb * 128;
        __syncthreads();   // A ready (nb=0) / all warps done with prev B

        // ---- Fill B block transposed: Bhi[n][k2] (coalesced n reads) ----
        #pragma unroll
        for (int i = 0; i < 32; i++) {
            int idx = t + i * 256;        // 0..8191
            int n   = idx & 127;
            int k2  = idx >> 7;           // k-pair 0..63
            float x0 = B[(size_t)(2 * k2)     * GI_COLS + n0 + n];
            float x1 = B[(size_t)(2 * k2 + 1) * GI_COLS + n0 + n];
            __nv_bfloat16 h0 = __float2bfloat16(x0);
            __nv_bfloat16 h1 = __float2bfloat16(x1);
            Bhi[n * WST + k2] = pkbf2(h0, h1);
            __nv_bfloat16 l0 = __float2bfloat16(x0 - __bfloat162float(h0));
            __nv_bfloat16 l1 = __float2bfloat16(x1 - __bfloat162float(h1));
            Blo[n * WST + k2] = pkbf2(l0, l1);
        }
        __syncthreads();

        float acc[4][4][4];
        #pragma unroll
        for (int ms = 0; ms < 4; ms++)
            #pragma unroll
            for (int ns = 0; ns < 4; ns++)
                #pragma unroll
                for (int x = 0; x < 4; x++) acc[ms][ns][x] = 0.0f;

        #pragma unroll
        for (int ks = 0; ks < 8; ks++) {
            unsigned ah[4][4], al[4][4], bh[4][2], bl[4][2];
            #pragma unroll
            for (int ms = 0; ms < 4; ms++) {
                uint32_t ao = aoff + (uint32_t)ms * (16 * WST * 4) +
                              (uint32_t)ks * 32;
                LDSM_X4(ah[ms][0], ah[ms][1], ah[ms][2], ah[ms][3], sAhi + ao);
                LDSM_X4(al[ms][0], al[ms][1], al[ms][2], al[ms][3], sAlo + ao);
            }
            #pragma unroll
            for (int np = 0; np < 2; np++) {
                uint32_t bo = boff + (uint32_t)np * (16 * WST * 4) +
                              (uint32_t)ks * 32;
                LDSM_X4(bh[2 * np][0], bh[2 * np][1],
                        bh[2 * np + 1][0], bh[2 * np + 1][1], sBhi + bo);
                LDSM_X4(bl[2 * np][0], bl[2 * np][1],
                        bl[2 * np + 1][0], bl[2 * np + 1][1], sBlo + bo);
            }
            #pragma unroll
            for (int ms = 0; ms < 4; ms++)
                #pragma unroll
                for (int ns = 0; ns < 4; ns++) {
                    MMA16816(acc[ms][ns], ah[ms], bh[ns]);
                    MMA16816(acc[ms][ns], al[ms], bh[ns]);
                    MMA16816(acc[ms][ns], ah[ms], bl[ns]);
                }
        }

        // ---- Epilogue: add bias, store ----
        #pragma unroll
        for (int ns = 0; ns < 4; ns++) {
            int c = n0 + wn * 32 + ns * 8 + 2 * q;
            float b0 = bias[c], b1 = bias[c + 1];
            #pragma unroll
            for (int ms = 0; ms < 4; ms++) {
                int rg = m0 + wm * 64 + ms * 16 + g;
                float2 v0 = make_float2(acc[ms][ns][0] + b0,
                                        acc[ms][ns][1] + b1);
                float2 v1 = make_float2(acc[ms][ns][2] + b0,
                                        acc[ms][ns][3] + b1);
                *reinterpret_cast<float2*>(g_gi + (size_t)rg * GI_COLS + c) = v0;
                *reinterpret_cast<float2*>(
                    g_gi + (size_t)(rg + 8) * GI_COLS + c) = v1;
            }
        }
    }
}

// ---------------------------------------------------------------------------
// Phase 2: sequential GRU scan (unchanged R8 winner). 128 CTAs x 512 threads,
// 2 envs/CTA; register-resident hidden weights; gi staged one step ahead via
// cp.async; resets in SMEM table.
// ---------------------------------------------------------------------------
__global__ __launch_bounds__(512, 1)
void gru_scan_kernel(const float* __restrict__ hidden0,
                     const unsigned char* __restrict__ resets_raw,
                     const float* __restrict__ Whr,
                     const float* __restrict__ Whz,
                     const float* __restrict__ Whn,
                     const float* __restrict__ bhn,
                     float* __restrict__ out_final,
                     float* __restrict__ out_ys) {
    __shared__ __align__(16) float hsm[2][FEAT];
    __shared__ float part[2][3][4][FEAT];       // [env][gate][kgroup][f]
    __shared__ __align__(16) float gibuf[2][2 * GI_COLS];
    __shared__ unsigned char rs2[T_STEPS * 2];  // [t][env]

    const int tid = threadIdx.x;
    const int f   = tid & 127;
    const int kg  = tid >> 7;       // 0..3
    const int k0  = kg * 32;
    const int envBase = blockIdx.x * 2;

    int local = 0;
    for (int i = tid; i < 4096; i += 512)
        if ((i & 3) != 0 && resets_raw[i] != 0) local = 1;
    const bool bmode = __syncthreads_or(local);
    const int* resets_i = reinterpret_cast<const int*>(resets_raw);

    const unsigned gib0 = smem_u32(&gibuf[0][0]);
    const unsigned gib1 = smem_u32(&gibuf[1][0]);
    if (tid < 192) {
        const float* src = g_gi + (size_t)envBase * GI_COLS + tid * 4;
        CP_ASYNC16(gib0 + tid * 16, src);
        CP_COMMIT();
    }

    for (int i = tid; i < T_STEPS * 2; i += 512) {
        int tt = i >> 1, e = i & 1;
        int gidx = tt * NENV + envBase + e;
        rs2[i] = bmode ? (resets_raw[gidx] != 0) : (resets_i[gidx] != 0);
    }

    ull wr2[16], wz2[16], wn2[16];
    #pragma unroll
    for (int j = 0; j < 16; j++) {
        int k = k0 + 2 * j;
        wr2[j] = pack2(Whr[k * FEAT + f], Whr[(k + 1) * FEAT + f]);
        wz2[j] = pack2(Whz[k * FEAT + f], Whz[(k + 1) * FEAT + f]);
        wn2[j] = pack2(Whn[k * FEAT + f], Whn[(k + 1) * FEAT + f]);
    }
    const float bn = bhn[f];
    __syncthreads();   // rs2 visible

    if (kg < 2) {
        int e = kg, env = envBase + e;
        float h0 = hidden0[env * FEAT + f];
        hsm[e][f] = rs2[e] ? 0.0f : h0;
    }
    __syncthreads();

    float finalh = 0.0f;

    #pragma unroll 1
    for (int t = 0; t < T_STEPS; t++) {
        const int p = t & 1;

        if (tid < 192) {
            int tn = (t + 1 < T_STEPS) ? (t + 1) : t;
            const float* src =
                g_gi + ((size_t)tn * NENV + envBase) * GI_COLS + tid * 4;
            CP_ASYNC16((p ? gib0 : gib1) + tid * 16, src);
            CP_COMMIT();
        }

        #pragma unroll
        for (int e = 0; e < 2; e++) {
            ull ar = 0ull, az = 0ull, an = 0ull;
            const ull* h64 = reinterpret_cast<const ull*>(&hsm[e][k0]);
            #pragma unroll
            for (int j = 0; j < 16; j++) {
                ull h2 = h64[j];
                FMA2(ar, h2, wr2[j], ar);
                FMA2(az, h2, wz2[j], az);
                FMA2(an, h2, wn2[j], an);
            }
            float lo, hi;
            unpack2(lo, hi, ar); part[e][0][kg][f] = lo + hi;
            unpack2(lo, hi, az); part[e][1][kg][f] = lo + hi;
            unpack2(lo, hi, an); part[e][2][kg][f] = lo + hi;
        }
        if (tid < 192) CP_WAIT1();
        __syncthreads();

        if (kg < 2) {
            int e = kg, env = envBase + e;
            const float* gb = &gibuf[p][e * GI_COLS];
            float gr = gb[f], gz = gb[FEAT + f], gn = gb[2 * FEAT + f];
            float sr = part[e][0][0][f] + part[e][0][1][f] +
                       part[e][0][2][f] + part[e][0][3][f];
            float sz = part[e][1][0][f] + part[e][1][1][f] +
                       part[e][1][2][f] + part[e][1][3][f];
            float sn = part[e][2][0][f] + part[e][2][1][f] +
                       part[e][2][2][f] + part[e][2][3][f];
            float r = sigmoidapx(gr + sr);
            float z = sigmoidapx(gz + sz);
            float n = tanhapx(gn + r * (sn + bn));
            float hold = hsm[e][f];
            float hnew = (1.0f - z) * n + z * hold;
            out_ys[(size_t)(t * NENV + env) * FEAT + f] = hnew;
            bool nextdone = (t + 1 < T_STEPS) ? (rs2[(t + 1) * 2 + e] != 0)
                                              : false;
            hsm[e][f] = nextdone ? 0.0f : hnew;
            if (t == T_STEPS - 1) finalh = hnew;
        }
        __syncthreads();
    }

    if (kg < 2) {
        int env = envBase + kg;
        out_final[env * FEAT + f] = finalh;
    }
}

// ---------------------------------------------------------------------------
// Launch
// Inputs: 0 hidden_state [N,F], 1 obs [T,N,D], 2 resets [T,N] (bool/int32),
//         3 Wi [D,3F], 4 bi [3F], 5 Whr, 6 Whz, 7 Whn [F,F], 8 bhn [F]
// Output: final_h [N,F] followed by ys [T,N,F]
// ---------------------------------------------------------------------------
extern "C" void kernel_launch(void* const* d_in, const int* in_sizes, int n_in,
                              void* d_out, int out_size) {
    const float*         hidden = (const float*)d_in[0];
    const float*         obs    = (const float*)d_in[1];
    const unsigned char* resets = (const unsigned char*)d_in[2];
    const float*         Wi     = (const float*)d_in[3];
    const float*         bi     = (const float*)d_in[4];
    const float*         Whr    = (const float*)d_in[5];
    const float*         Whz    = (const float*)d_in[6];
    const float*         Whn    = (const float*)d_in[7];
    const float*         bhn    = (const float*)d_in[8];

    float* out       = (float*)d_out;
    float* out_final = out;                       // [N*F]
    float* out_ys    = out + NENV * FEAT;         // [T*N*F]

    const int smem_bytes = 4 * 128 * WST * (int)sizeof(unsigned);  // 139264
    static int attr_set = 0;
    if (!attr_set) {
        cudaFuncSetAttribute(gemm_gi_bf16_kernel,
                             cudaFuncAttributeMaxDynamicSharedMemorySize,
                             smem_bytes);
        attr_set = 1;
    }

    gemm_gi_bf16_kernel<<<(T_STEPS * NENV) / 128, 256, smem_bytes>>>(obs, Wi, bi);

    gru_scan_kernel<<<NENV / 2, 512>>>(hidden, resets, Whr, Whz, Whn, bhn,
                                       out_final, out_ys);
}

// round 17
// speedup vs baseline: 1.1815x; 1.1815x over previous
#include <cuda_runtime.h>
#include <cuda_bf16.h>
#include <cstdint>
#include <cstddef>

#define T_STEPS 1024
#define NENV    256
#define DIM     128
#define FEAT    128
#define GI_COLS 384   // 3*F

typedef unsigned long long ull;

// Scratch for precomputed input projections gi = obs @ Wi + bi  : [T*N, 3F]
__device__ float g_gi[(size_t)T_STEPS * NENV * GI_COLS];

// ---- packed f32x2 helpers ------------------------------------------------
#define FMA2(d, a, b, c) \
    asm("fma.rn.f32x2 %0, %1, %2, %3;" : "=l"(d) : "l"(a), "l"(b), "l"(c))

__device__ __forceinline__ ull pack2(float lo, float hi) {
    ull r;
    asm("mov.b64 %0, {%1, %2};" : "=l"(r)
        : "r"(__float_as_uint(lo)), "r"(__float_as_uint(hi)));
    return r;
}
__device__ __forceinline__ void unpack2(float& lo, float& hi, ull v) {
    unsigned a, b;
    asm("mov.b64 {%0, %1}, %2;" : "=r"(a), "=r"(b) : "l"(v));
    lo = __uint_as_float(a);
    hi = __uint_as_float(b);
}
__device__ __forceinline__ float tanhapx(float x) {
    float y;
    asm("tanh.approx.f32 %0, %1;" : "=f"(y) : "f"(x));
    return y;
}
__device__ __forceinline__ float sigmoidapx(float x) {
    return fmaf(0.5f, tanhapx(0.5f * x), 0.5f);
}
__device__ __forceinline__ unsigned smem_u32(const void* p) {
    unsigned a;
    asm("{ .reg .u64 t; cvta.to.shared.u64 t, %1; cvt.u32.u64 %0, t; }"
        : "=r"(a) : "l"(p));
    return a;
}
#define CP_ASYNC16(dst_u32, src_ptr) \
    asm volatile("cp.async.cg.shared.global [%0], [%1], 16;" \
                 :: "r"(dst_u32), "l"(src_ptr))
#define CP_COMMIT() asm volatile("cp.async.commit_group;")
#define CP_WAIT1()  asm volatile("cp.async.wait_group 1;")

// ---- bf16 split helpers ---------------------------------------------------
__device__ __forceinline__ unsigned pkbf2(__nv_bfloat16 b0, __nv_bfloat16 b1) {
    return ((unsigned)__bfloat16_as_ushort(b1) << 16) |
           (unsigned)__bfloat16_as_ushort(b0);
}

#define MMA16816(d, a, b) \
    asm volatile("mma.sync.aligned.m16n8k16.row.col.f32.bf16.bf16.f32 " \
        "{%0,%1,%2,%3}, {%4,%5,%6,%7}, {%8,%9}, {%0,%1,%2,%3};" \
        : "+f"((d)[0]), "+f"((d)[1]), "+f"((d)[2]), "+f"((d)[3]) \
        : "r"((a)[0]), "r"((a)[1]), "r"((a)[2]), "r"((a)[3]), \
          "r"((b)[0]), "r"((b)[1]))

#define LDSM_X4(r0, r1, r2, r3, addr) \
    asm volatile("ldmatrix.sync.aligned.m8n8.x4.shared.b16 {%0,%1,%2,%3}, [%4];" \
        : "=r"(r0), "=r"(r1), "=r"(r2), "=r"(r3) : "r"(addr))

// ---------------------------------------------------------------------------
// Phase 1: gi = obs @ Wi + bi  via bf16 3-term split tensor-core GEMM.
//   A@B ~= Ah Bh + Al Bh + Ah Bl   (fp32 accumulate; rel err ~1e-5)
// CTA: 128m block, full K in SMEM, loops over 3 n-blocks of 128.
// 256 threads = 8 warps (2m x 4n), warp tile 64x32, mma m16n8k16,
// fragment loads via ldmatrix.x4.
// ---------------------------------------------------------------------------
#define WST 68   // row stride in 32-bit words (= 136 bf16)

__global__ __launch_bounds__(256)
void gemm_gi_bf16_kernel(const float* __restrict__ A,
                         const float* __restrict__ B,
                         const float* __restrict__ bias) {
    extern __shared__ unsigned smw[];
    unsigned* Ahi = smw;                  // [128][WST]
    unsigned* Alo = Ahi + 128 * WST;
    unsigned* Bhi = Alo + 128 * WST;      // [n][k-pairs]
    unsigned* Blo = Bhi + 128 * WST;

    const int t    = threadIdx.x;
    const int m0   = blockIdx.x * 128;
    const int warp = t >> 5;
    const int lane = t & 31;
    const int g    = lane >> 2;      // 0..7
    const int q    = lane & 3;       // 0..3
    const int wm   = warp >> 2;      // 0..1
    const int wn   = warp & 3;       // 0..3

    // ---- Fill A (obs block, full K), split hi/lo ----
    #pragma unroll
    for (int i = 0; i < 16; i++) {
        int idx = t + i * 256;            // 0..4095 float4 slots
        int m   = idx >> 5;               // 0..127
        int kc  = (idx & 31) << 2;        // 0..124
        float4 v = *reinterpret_cast<const float4*>(
            A + (size_t)(m0 + m) * 128 + kc);
        __nv_bfloat16 hx = __float2bfloat16(v.x), hy = __float2bfloat16(v.y);
        __nv_bfloat16 hz = __float2bfloat16(v.z), hw = __float2bfloat16(v.w);
        Ahi[m * WST + (kc >> 1)]     = pkbf2(hx, hy);
        Ahi[m * WST + (kc >> 1) + 1] = pkbf2(hz, hw);
        __nv_bfloat16 lx = __float2bfloat16(v.x - __bfloat162float(hx));
        __nv_bfloat16 ly = __float2bfloat16(v.y - __bfloat162float(hy));
        __nv_bfloat16 lz = __float2bfloat16(v.z - __bfloat162float(hz));
        __nv_bfloat16 lw = __float2bfloat16(v.w - __bfloat162float(hw));
        Alo[m * WST + (kc >> 1)]     = pkbf2(lx, ly);
        Alo[m * WST + (kc >> 1) + 1] = pkbf2(lz, lw);
    }

    const uint32_t sAhi = smem_u32(Ahi);
    const uint32_t sAlo = smem_u32(Alo);
    const uint32_t sBhi = smem_u32(Bhi);
    const uint32_t sBlo = smem_u32(Blo);
    const uint32_t aoff =
        ((uint32_t)(wm * 64 + (lane & 15)) * WST + (uint32_t)(lane >> 4) * 4) * 4u;
    const uint32_t boff =
        ((uint32_t)(wn * 32 + (lane & 7) + ((lane >> 4) << 3)) * WST +
         (uint32_t)((lane >> 3) & 1) * 4) * 4u;

    for (int nb = 0; nb < 3; nb++) {
        const int n0 = nb * 128;
        __syncthreads();   // A ready (nb=0) / all warps done with prev B

        // ---- Fill B block transposed: Bhi[n][k2] ----
        #pragma unroll
        for (int i = 0; i < 32; i++) {
            int idx = t + i * 256;        // 0..8191
            int n   = idx & 127;
            int k2  = idx >> 7;           // k-pair 0..63
            float x0 = B[(size_t)(2 * k2)     * GI_COLS + n0 + n];
            float x1 = B[(size_t)(2 * k2 + 1) * GI_COLS + n0 + n];
            __nv_bfloat16 h0 = __float2bfloat16(x0);
            __nv_bfloat16 h1 = __float2bfloat16(x1);
            Bhi[n * WST + k2] = pkbf2(h0, h1);
            __nv_bfloat16 l0 = __float2bfloat16(x0 - __bfloat162float(h0));
            __nv_bfloat16 l1 = __float2bfloat16(x1 - __bfloat162float(h1));
            Blo[n * WST + k2] = pkbf2(l0, l1);
        }
        __syncthreads();

        float acc[4][4][4];
        #pragma unroll
        for (int ms = 0; ms < 4; ms++)
            #pragma unroll
            for (int ns = 0; ns < 4; ns++)
                #pragma unroll
                for (int x = 0; x < 4; x++) acc[ms][ns][x] = 0.0f;

        #pragma unroll
        for (int ks = 0; ks < 8; ks++) {
            unsigned ah[4][4], al[4][4], bh[4][2], bl[4][2];
            #pragma unroll
            for (int ms = 0; ms < 4; ms++) {
                uint32_t ao = aoff + (uint32_t)ms * (16 * WST * 4) +
                              (uint32_t)ks * 32;
                LDSM_X4(ah[ms][0], ah[ms][1], ah[ms][2], ah[ms][3], sAhi + ao);
                LDSM_X4(al[ms][0], al[ms][1], al[ms][2], al[ms][3], sAlo + ao);
            }
            #pragma unroll
            for (int np = 0; np < 2; np++) {
                uint32_t bo = boff + (uint32_t)np * (16 * WST * 4) +
                              (uint32_t)ks * 32;
                LDSM_X4(bh[2 * np][0], bh[2 * np][1],
                        bh[2 * np + 1][0], bh[2 * np + 1][1], sBhi + bo);
                LDSM_X4(bl[2 * np][0], bl[2 * np][1],
                        bl[2 * np + 1][0], bl[2 * np + 1][1], sBlo + bo);
            }
            #pragma unroll
            for (int ms = 0; ms < 4; ms++)
                #pragma unroll
                for (int ns = 0; ns < 4; ns++) {
                    MMA16816(acc[ms][ns], ah[ms], bh[ns]);
                    MMA16816(acc[ms][ns], al[ms], bh[ns]);
                    MMA16816(acc[ms][ns], ah[ms], bl[ns]);
                }
        }

        // ---- Epilogue: add bias, store ----
        #pragma unroll
        for (int ns = 0; ns < 4; ns++) {
            int c = n0 + wn * 32 + ns * 8 + 2 * q;
            float b0 = bias[c], b1 = bias[c + 1];
            #pragma unroll
            for (int ms = 0; ms < 4; ms++) {
                int rg = m0 + wm * 64 + ms * 16 + g;
                float2 v0 = make_float2(acc[ms][ns][0] + b0,
                                        acc[ms][ns][1] + b1);
                float2 v1 = make_float2(acc[ms][ns][2] + b0,
                                        acc[ms][ns][3] + b1);
                *reinterpret_cast<float2*>(g_gi + (size_t)rg * GI_COLS + c) = v0;
                *reinterpret_cast<float2*>(
                    g_gi + (size_t)(rg + 8) * GI_COLS + c) = v1;
            }
        }
    }
}

// ---------------------------------------------------------------------------
// Phase 2: sequential GRU scan. 128 CTAs x 512 threads, 2 envs/CTA;
// register-resident hidden weights; gi staged one step ahead via cp.async;
// resets in SMEM table.
// NEW: reset-skip — when rs2[t][e] is set, h entering this step is exactly 0
// (reset pre-applied), so the entire matvec for that env is exactly zero.
// Skip its 48 FMA2 with a CTA-uniform branch; finalize substitutes s = 0.
// Numerically exact; E[reset] = 0.5 halves expected matvec issue cost.
// ---------------------------------------------------------------------------
__global__ __launch_bounds__(512, 1)
void gru_scan_kernel(const float* __restrict__ hidden0,
                     const unsigned char* __restrict__ resets_raw,
                     const float* __restrict__ Whr,
                     const float* __restrict__ Whz,
                     const float* __restrict__ Whn,
                     const float* __restrict__ bhn,
                     float* __restrict__ out_final,
                     float* __restrict__ out_ys) {
    __shared__ __align__(16) float hsm[2][FEAT];
    __shared__ float part[2][3][4][FEAT];       // [env][gate][kgroup][f]
    __shared__ __align__(16) float gibuf[2][2 * GI_COLS];
    __shared__ unsigned char rs2[T_STEPS * 2];  // [t][env]

    const int tid = threadIdx.x;
    const int f   = tid & 127;
    const int kg  = tid >> 7;       // 0..3
    const int k0  = kg * 32;
    const int envBase = blockIdx.x * 2;

    int local = 0;
    for (int i = tid; i < 4096; i += 512)
        if ((i & 3) != 0 && resets_raw[i] != 0) local = 1;
    const bool bmode = __syncthreads_or(local);
    const int* resets_i = reinterpret_cast<const int*>(resets_raw);

    const unsigned gib0 = smem_u32(&gibuf[0][0]);
    const unsigned gib1 = smem_u32(&gibuf[1][0]);
    if (tid < 192) {
        const float* src = g_gi + (size_t)envBase * GI_COLS + tid * 4;
        CP_ASYNC16(gib0 + tid * 16, src);
        CP_COMMIT();
    }

    for (int i = tid; i < T_STEPS * 2; i += 512) {
        int tt = i >> 1, e = i & 1;
        int gidx = tt * NENV + envBase + e;
        rs2[i] = bmode ? (resets_raw[gidx] != 0) : (resets_i[gidx] != 0);
    }

    ull wr2[16], wz2[16], wn2[16];
    #pragma unroll
    for (int j = 0; j < 16; j++) {
        int k = k0 + 2 * j;
        wr2[j] = pack2(Whr[k * FEAT + f], Whr[(k + 1) * FEAT + f]);
        wz2[j] = pack2(Whz[k * FEAT + f], Whz[(k + 1) * FEAT + f]);
        wn2[j] = pack2(Whn[k * FEAT + f], Whn[(k + 1) * FEAT + f]);
    }
    const float bn = bhn[f];
    __syncthreads();   // rs2 visible

    if (kg < 2) {
        int e = kg, env = envBase + e;
        float h0 = hidden0[env * FEAT + f];
        hsm[e][f] = rs2[e] ? 0.0f : h0;
    }
    __syncthreads();

    float finalh = 0.0f;

    #pragma unroll 1
    for (int t = 0; t < T_STEPS; t++) {
        const int p = t & 1;

        if (tid < 192) {
            int tn = (t + 1 < T_STEPS) ? (t + 1) : t;
            const float* src =
                g_gi + ((size_t)tn * NENV + envBase) * GI_COLS + tid * 4;
            CP_ASYNC16((p ? gib0 : gib1) + tid * 16, src);
            CP_COMMIT();
        }

        // Matvec per env — skipped entirely (CTA-uniform branch) when the
        // env was just reset: h == 0 so every partial sum is exactly 0.
        #pragma unroll
        for (int e = 0; e < 2; e++) {
            if (rs2[t * 2 + e]) continue;
            ull ar = 0ull, az = 0ull, an = 0ull;
            const ull* h64 = reinterpret_cast<const ull*>(&hsm[e][k0]);
            #pragma unroll
            for (int j = 0; j < 16; j++) {
                ull h2 = h64[j];
                FMA2(ar, h2, wr2[j], ar);
                FMA2(az, h2, wz2[j], az);
                FMA2(an, h2, wn2[j], an);
            }
            float lo, hi;
            unpack2(lo, hi, ar); part[e][0][kg][f] = lo + hi;
            unpack2(lo, hi, az); part[e][1][kg][f] = lo + hi;
            unpack2(lo, hi, an); part[e][2][kg][f] = lo + hi;
        }
        if (tid < 192) CP_WAIT1();
        __syncthreads();

        if (kg < 2) {
            int e = kg, env = envBase + e;
            const bool wasreset = rs2[t * 2 + e] != 0;
            const float* gb = &gibuf[p][e * GI_COLS];
            float gr = gb[f], gz = gb[FEAT + f], gn = gb[2 * FEAT + f];
            float sr = 0.0f, sz = 0.0f, sn = 0.0f;
            if (!wasreset) {
                sr = part[e][0][0][f] + part[e][0][1][f] +
                     part[e][0][2][f] + part[e][0][3][f];
                sz = part[e][1][0][f] + part[e][1][1][f] +
                     part[e][1][2][f] + part[e][1][3][f];
                sn = part[e][2][0][f] + part[e][2][1][f] +
                     part[e][2][2][f] + part[e][2][3][f];
            }
            float r = sigmoidapx(gr + sr);
            float z = sigmoidapx(gz + sz);
            float n = tanhapx(gn + r * (sn + bn));
            float hold = wasreset ? 0.0f : hsm[e][f];
            float hnew = (1.0f - z) * n + z * hold;
            out_ys[(size_t)(t * NENV + env) * FEAT + f] = hnew;
            bool nextdone = (t + 1 < T_STEPS) ? (rs2[(t + 1) * 2 + e] != 0)
                                              : false;
            hsm[e][f] = nextdone ? 0.0f : hnew;
            if (t == T_STEPS - 1) finalh = hnew;
        }
        __syncthreads();
    }

    if (kg < 2) {
        int env = envBase + kg;
        out_final[env * FEAT + f] = finalh;
    }
}

// ---------------------------------------------------------------------------
// Launch
// Inputs: 0 hidden_state [N,F], 1 obs [T,N,D], 2 resets [T,N] (bool/int32),
//         3 Wi [D,3F], 4 bi [3F], 5 Whr, 6 Whz, 7 Whn [F,F], 8 bhn [F]
// Output: final_h [N,F] followed by ys [T,N,F]
// ---------------------------------------------------------------------------
extern "C" void kernel_launch(void* const* d_in, const int* in_sizes, int n_in,
                              void* d_out, int out_size) {
    const float*         hidden = (const float*)d_in[0];
    const float*         obs    = (const float*)d_in[1];
    const unsigned char* resets = (const unsigned char*)d_in[2];
    const float*         Wi     = (const float*)d_in[3];
    const float*         bi     = (const float*)d_in[4];
    const float*         Whr    = (const float*)d_in[5];
    const float*         Whz    = (const float*)d_in[6];
    const float*         Whn    = (const float*)d_in[7];
    const float*         bhn    = (const float*)d_in[8];

    float* out       = (float*)d_out;
    float* out_final = out;                       // [N*F]
    float* out_ys    = out + NENV * FEAT;         // [T*N*F]

    const int smem_bytes = 4 * 128 * WST * (int)sizeof(unsigned);  // 139264
    static int attr_set = 0;
    if (!attr_set) {
        cudaFuncSetAttribute(gemm_gi_bf16_kernel,
                             cudaFuncAttributeMaxDynamicSharedMemorySize,
                             smem_bytes);
        attr_set = 1;
    }

    gemm_gi_bf16_kernel<<<(T_STEPS * NENV) / 128, 256, smem_bytes>>>(obs, Wi, bi);

    gru_scan_kernel<<<NENV / 2, 512>>>(hidden, resets, Whr, Whz, Whn, bhn,
                                       out_final, out_ys);
}